// round 4
// baseline (speedup 1.0000x reference)
#include <cuda_runtime.h>

#define REC      2048
#define BATCH    64
#define RSTEPS   512
#define EDIM     512
#define KTOP     819
#define GRID     128      // persistent blocks: <= SM count, occupancy-1 guaranteed
#define NTHREADS 512
#define BK       16
#define NBAR     (1 + 2*RSTEPS)   // 1025 barriers per launch

// ---- static device scratch (no allocations anywhere) ----------------------
__device__ float g_R[BATCH * REC];                       // recurrent state
__device__ float g_part[8 * BATCH * REC];                // K-split partials
__device__ float g_U[(size_t)RSTEPS * BATCH * REC];      // precomputed x @ W_in
__device__ unsigned g_bar;                               // grid barrier counter

// Order-preserving float -> uint32 key (ascending).
__device__ __forceinline__ unsigned keyOf(float f) {
    unsigned b = __float_as_uint(f);
    return (b & 0x80000000u) ? ~b : (b | 0x80000000u);
}

// ---------------------------------------------------------------------------
// Precompute U[t][b][:] = x[b,t,:] @ W_input.   M=32768, N=2048, K=512.
// Tile 64(M=batch within fixed t) x 128(N) x 512(K), double-buffered.
// ---------------------------------------------------------------------------
__global__ void __launch_bounds__(NTHREADS) precompute_u_kernel(
    const float* __restrict__ x, const float* __restrict__ Wi)
{
    __shared__ float As[2][BK][68];
    __shared__ float Ws[2][BK][128];

    const int t   = blockIdx.y;            // time index 0..511
    const int n0  = blockIdx.x * 128;
    const int tid = threadIdx.x;
    const int tm  = tid >> 5, tn = tid & 31;
    const int alm = tid >> 2, alk4 = (tid & 3) << 2;   // A loaders: tid<256
    const int blk = tid >> 5, bln4 = (tid & 31) << 2;  // B loaders: all

    float acc[4][4];
    #pragma unroll
    for (int i = 0; i < 4; i++)
        #pragma unroll
        for (int j = 0; j < 4; j++) acc[i][j] = 0.0f;

    float4 a4, b4;
    if (tid < 256)
        a4 = *(const float4*)&x[((size_t)alm * RSTEPS + t) * EDIM + alk4];
    b4 = *(const float4*)&Wi[(size_t)blk * REC + n0 + bln4];

    int buf = 0;
    if (tid < 256) {
        As[buf][alk4+0][alm] = a4.x; As[buf][alk4+1][alm] = a4.y;
        As[buf][alk4+2][alm] = a4.z; As[buf][alk4+3][alm] = a4.w;
    }
    *(float4*)&Ws[buf][blk][bln4] = b4;
    __syncthreads();

    #pragma unroll 1
    for (int it = 0; it < EDIM / BK; it++) {
        const int k1 = (it + 1) * BK;
        const bool more = (k1 < EDIM);
        if (more) {
            if (tid < 256)
                a4 = *(const float4*)&x[((size_t)alm * RSTEPS + t) * EDIM + k1 + alk4];
            b4 = *(const float4*)&Wi[(size_t)(k1 + blk) * REC + n0 + bln4];
        }
        #pragma unroll
        for (int kk = 0; kk < BK; kk++) {
            float4 a = *(const float4*)&As[buf][kk][tm << 2];
            float4 b = *(const float4*)&Ws[buf][kk][tn << 2];
            float av[4] = {a.x, a.y, a.z, a.w};
            float bv[4] = {b.x, b.y, b.z, b.w};
            #pragma unroll
            for (int i = 0; i < 4; i++)
                #pragma unroll
                for (int j = 0; j < 4; j++)
                    acc[i][j] = fmaf(av[i], bv[j], acc[i][j]);
        }
        if (more) {
            if (tid < 256) {
                As[buf^1][alk4+0][alm] = a4.x; As[buf^1][alk4+1][alm] = a4.y;
                As[buf^1][alk4+2][alm] = a4.z; As[buf^1][alk4+3][alm] = a4.w;
            }
            *(float4*)&Ws[buf^1][blk][bln4] = b4;
        }
        __syncthreads();
        buf ^= 1;
    }

    #pragma unroll
    for (int i = 0; i < 4; i++) {
        int b = (tm << 2) + i;
        *(float4*)&g_U[((size_t)t * BATCH + b) * REC + n0 + (tn << 2)] =
            make_float4(acc[i][0], acc[i][1], acc[i][2], acc[i][3]);
    }
}

// ---------------------------------------------------------------------------
// Persistent scan kernel: 128 co-resident blocks, software grid barriers.
// Per step: phase A = 16(N-tiles of 128) x 8(K-chunks of 256) GEMM tiles, one
// per block, writing K-split partials; phase B = blocks 0..63 reduce + exact
// radix top-k threshold + tanh + L2-normalize, updating g_R.
// ---------------------------------------------------------------------------
__device__ __forceinline__ void grid_barrier(unsigned target) {
    __syncthreads();
    if (threadIdx.x == 0) {
        __threadfence();                    // publish my writes
        atomicAdd(&g_bar, 1u);
        while (*(volatile unsigned*)&g_bar < target) { __nanosleep(40); }
        __threadfence();                    // CCTL.IVALL: drop stale L1 lines
    }
    __syncthreads();
}

__global__ void __launch_bounds__(NTHREADS) persist_kernel(
    const float* __restrict__ Wr, float* __restrict__ out)
{
    __shared__ float As[2][BK][68];
    __shared__ float Ws[2][BK][128];
    __shared__ float zrow[REC];
    __shared__ float urow[REC];
    __shared__ unsigned hist[256];
    __shared__ unsigned sh_prefix, sh_k;
    __shared__ float red[16];

    const int bid = blockIdx.x;
    const int tid = threadIdx.x;

    // zero the recurrent state
    for (int i = bid * NTHREADS + tid; i < BATCH * REC; i += GRID * NTHREADS)
        g_R[i] = 0.0f;
    unsigned baridx = 1;
    grid_barrier(baridx * GRID);

    // phase-A tile assignment (fixed per block)
    const int ntile = bid & 15;
    const int kc    = bid >> 4;
    const int n0    = ntile * 128;
    const int kbase = kc * 256;
    const int tm  = tid >> 5, tn = tid & 31;
    const int alm = tid >> 2, alk4 = (tid & 3) << 2;
    const int blk = tid >> 5, bln4 = (tid & 31) << 2;
    const int m   = bid;                       // phase-B row

    for (int step = 0; step < RSTEPS; step++) {
        // ---------------- phase A: partial = r[:,kc] @ Wr[kc, ntile] -------
        {
            float acc[4][4];
            #pragma unroll
            for (int i = 0; i < 4; i++)
                #pragma unroll
                for (int j = 0; j < 4; j++) acc[i][j] = 0.0f;

            float4 a4, b4;
            if (tid < 256)
                a4 = *(const float4*)&g_R[(size_t)alm * REC + kbase + alk4];
            b4 = *(const float4*)&Wr[(size_t)(kbase + blk) * REC + n0 + bln4];

            int buf = 0;
            if (tid < 256) {
                As[buf][alk4+0][alm] = a4.x; As[buf][alk4+1][alm] = a4.y;
                As[buf][alk4+2][alm] = a4.z; As[buf][alk4+3][alm] = a4.w;
            }
            *(float4*)&Ws[buf][blk][bln4] = b4;
            __syncthreads();

            #pragma unroll 1
            for (int it = 0; it < 256 / BK; it++) {
                const int k1 = (it + 1) * BK;
                const bool more = (k1 < 256);
                if (more) {
                    if (tid < 256)
                        a4 = *(const float4*)&g_R[(size_t)alm * REC + kbase + k1 + alk4];
                    b4 = *(const float4*)&Wr[(size_t)(kbase + k1 + blk) * REC + n0 + bln4];
                }
                #pragma unroll
                for (int kk = 0; kk < BK; kk++) {
                    float4 a = *(const float4*)&As[buf][kk][tm << 2];
                    float4 b = *(const float4*)&Ws[buf][kk][tn << 2];
                    float av[4] = {a.x, a.y, a.z, a.w};
                    float bv[4] = {b.x, b.y, b.z, b.w};
                    #pragma unroll
                    for (int i = 0; i < 4; i++)
                        #pragma unroll
                        for (int j = 0; j < 4; j++)
                            acc[i][j] = fmaf(av[i], bv[j], acc[i][j]);
                }
                if (more) {
                    if (tid < 256) {
                        As[buf^1][alk4+0][alm] = a4.x; As[buf^1][alk4+1][alm] = a4.y;
                        As[buf^1][alk4+2][alm] = a4.z; As[buf^1][alk4+3][alm] = a4.w;
                    }
                    *(float4*)&Ws[buf^1][blk][bln4] = b4;
                }
                __syncthreads();
                buf ^= 1;
            }

            #pragma unroll
            for (int i = 0; i < 4; i++) {
                int row = (tm << 2) + i;
                *(float4*)&g_part[((size_t)kc * BATCH + row) * REC + n0 + (tn << 2)] =
                    make_float4(acc[i][0], acc[i][1], acc[i][2], acc[i][3]);
            }
        }
        baridx++;
        grid_barrier(baridx * GRID);

        // ---------------- phase B: reduce + top-k + tanh + normalize -------
        if (bid < BATCH) {
            for (int j = tid; j < REC; j += NTHREADS) {
                float zz = 0.0f;
                #pragma unroll
                for (int c = 0; c < 8; c++)
                    zz += g_part[((size_t)c * BATCH + m) * REC + j];
                zrow[j] = zz;
                urow[j] = g_U[((size_t)step * BATCH + m) * REC + j];
            }
            if (tid == 0) { sh_prefix = 0u; sh_k = KTOP; }
            __syncthreads();

            #pragma unroll
            for (int shift = 24; shift >= 0; shift -= 8) {
                if (tid < 256) hist[tid] = 0u;
                __syncthreads();
                unsigned prefix = sh_prefix;
                unsigned maskH  = (shift == 24) ? 0u : (0xFFFFFFFFu << (shift + 8));
                for (int j = tid; j < REC; j += NTHREADS) {
                    unsigned key = keyOf(zrow[j]);
                    if (((key ^ prefix) & maskH) == 0u)
                        atomicAdd(&hist[(key >> shift) & 0xFFu], 1u);
                }
                __syncthreads();
                if (tid == 0) {
                    unsigned k = sh_k, cum = 0u;
                    int b2 = 255;
                    for (; b2 >= 0; b2--) { cum += hist[b2]; if (cum >= k) break; }
                    sh_k = k - (cum - hist[b2]);
                    sh_prefix = prefix | ((unsigned)b2 << shift);
                }
                __syncthreads();
            }
            const unsigned thKey = sh_prefix;

            float part = 0.0f;
            for (int j = tid; j < REC; j += NTHREADS) {
                float zz = zrow[j];
                float s  = (keyOf(zz) >= thKey) ? zz : 0.0f;
                float v  = tanhf(urow[j] + s);
                zrow[j]  = v;
                part += v * v;
            }
            #pragma unroll
            for (int o = 16; o > 0; o >>= 1)
                part += __shfl_down_sync(0xFFFFFFFFu, part, o);
            if ((tid & 31) == 0) red[tid >> 5] = part;
            __syncthreads();
            if (tid < 32) {
                float v = (tid < 16) ? red[tid] : 0.0f;
                #pragma unroll
                for (int o = 8; o > 0; o >>= 1)
                    v += __shfl_down_sync(0xFFFFFFFFu, v, o);
                if (tid == 0) red[0] = v;
            }
            __syncthreads();
            const float inv = 1.0f / (sqrtf(red[0]) + 1e-6f);
            for (int j = tid; j < REC; j += NTHREADS) {
                float v = zrow[j] * inv;
                g_R[(size_t)m * REC + j] = v;
                if (step == RSTEPS - 1) out[(size_t)m * REC + j] = v;
            }
        }
        baridx++;
        if (step < RSTEPS - 1) {
            grid_barrier(baridx * GRID);
        } else {
            // final: arrive-only; last arriver resets the counter for replay
            __syncthreads();
            if (tid == 0) {
                __threadfence();
                unsigned p = atomicAdd(&g_bar, 1u);
                if (p == (unsigned)NBAR * GRID - 1u) atomicExch(&g_bar, 0u);
            }
        }
    }
}

// ---------------------------------------------------------------------------
extern "C" void kernel_launch(void* const* d_in, const int* in_sizes, int n_in,
                              void* d_out, int out_size)
{
    // identify inputs by distinct element counts
    const float* x  = nullptr;   // 64*512*512  = 16777216
    const float* Wi = nullptr;   // 512*2048    = 1048576
    const float* Wr = nullptr;   // 2048*2048   = 4194304
    for (int i = 0; i < n_in; i++) {
        if      (in_sizes[i] == BATCH * RSTEPS * EDIM) x  = (const float*)d_in[i];
        else if (in_sizes[i] == EDIM * REC)            Wi = (const float*)d_in[i];
        else if (in_sizes[i] == REC * REC)             Wr = (const float*)d_in[i];
    }
    float* out = (float*)d_out;

    precompute_u_kernel<<<dim3(REC / 128, RSTEPS), NTHREADS>>>(x, Wi);
    persist_kernel<<<GRID, NTHREADS>>>(Wr, out);
}